// round 2
// baseline (speedup 1.0000x reference)
#include <cuda_runtime.h>
#include <cuda_bf16.h>
#include <math.h>

// Problem shape (fixed by dataset): T=512, N=512, C=80, S=128
#define TT 512
#define CC 80
#define SS 128
#define LL 257            // 2*S + 1
#define NEGV (-1e30f)
#define NTHREADS 288      // 9 warps; threads [257,288) idle in compute, join syncs

__global__ __launch_bounds__(NTHREADS, 7)
void ctc_loss_kernel(const float* __restrict__ log_probs,   // (T, N, C)
                     const int*   __restrict__ targets,     // (N, S)
                     const int*   __restrict__ input_lengths,   // (N,)
                     const int*   __restrict__ target_lengths,  // (N,)
                     float*       __restrict__ out,         // (N,)
                     int N)
{
    __shared__ __align__(16) float shE[2][CC];  // emission row ping-pong (16B for float4)
    __shared__ float shA[2][LL];                // alpha double buffer

    const int n   = blockIdx.x;
    const int s   = threadIdx.x;
    const int len = input_lengths[n];     // >= 1 (dataset: >= T/2)
    const int tl  = target_lengths[n];    // >= 1

    // Time-invariant per-position state: label class + skip permission (registers)
    int  myc  = 0;       // ext[s]: 0 (blank) for even s, targets[n][s>>1] for odd s
    bool skip = false;   // s-2 -> s allowed iff s odd, s>=3, ext[s] != ext[s-2]
    if (s < LL && (s & 1)) {
        int j = s >> 1;
        myc = targets[n * SS + j];
        if (s >= 2) skip = (myc != targets[n * SS + j - 1]);
    }

    const float*  lp      = log_probs + (size_t)n * CC;
    const size_t  tstride = (size_t)N * CC;

    // ---- prologue: emit[t=0] ----
    if (threadIdx.x < CC / 4) {
        ((float4*)shE[0])[threadIdx.x] = ((const float4*)lp)[threadIdx.x];
    }
    __syncthreads();

    // alpha(t=0): only s=0 (blank) and s=1 (first label) reachable
    if (s < LL) {
        shA[0][s] = (s <= 1) ? shE[0][myc] : NEGV;
    }
    // prefetch emit[t=1]
    if (threadIdx.x < CC / 4 && len > 1) {
        ((float4*)shE[1])[threadIdx.x] = ((const float4*)(lp + tstride))[threadIdx.x];
    }
    __syncthreads();

    // ---- main DP: iterate only t < len (frozen steps are identity) ----
    int cur = 0;
    for (int t = 1; t < len; ++t) {
        const int eb = t & 1;

        // prefetch emission for t+1 (issued early; latency hidden by compute)
        float4 pre;
        const bool doP = (threadIdx.x < CC / 4) && (t + 1 < len);
        if (doP) pre = ((const float4*)(lp + (size_t)(t + 1) * tstride))[threadIdx.x];

        float nv;
        if (s < LL) {
            float a0 = shA[cur][s];
            float a1 = (s >= 1) ? shA[cur][s - 1] : NEGV;
            float a2 = skip     ? shA[cur][s - 2] : NEGV;
            float m  = fmaxf(a0, fmaxf(a1, a2));
            // exact 3-way log-sum-exp
            float sum = __expf(a0 - m) + __expf(a1 - m) + __expf(a2 - m);
            nv = m + __logf(sum) + shE[eb][myc];
        }

        if (doP) ((float4*)shE[eb ^ 1])[threadIdx.x] = pre;
        if (s < LL) shA[cur ^ 1][s] = nv;
        __syncthreads();
        cur ^= 1;
    }

    // ---- epilogue: combine final blank (2*tl) and final label (2*tl-1) ----
    if (threadIdx.x == 0) {
        int   i1 = 2 * tl;
        float v1 = shA[cur][i1];
        float v2 = shA[cur][i1 - 1];
        float m  = fmaxf(v1, v2);
        float loss = -(m + __logf(__expf(v1 - m) + __expf(v2 - m)));
        // zero_infinity: infeasible / huge -> 0
        if (!isfinite(loss) || loss >= 1e10f) loss = 0.0f;
        out[n] = loss;
    }
}

extern "C" void kernel_launch(void* const* d_in, const int* in_sizes, int n_in,
                              void* d_out, int out_size)
{
    const float* log_probs      = (const float*)d_in[0];
    const int*   targets        = (const int*)  d_in[1];
    const int*   input_lengths  = (const int*)  d_in[2];
    const int*   target_lengths = (const int*)  d_in[3];
    float*       out            = (float*)d_out;

    const int N = in_sizes[2];   // batch from input_lengths element count

    ctc_loss_kernel<<<N, NTHREADS>>>(log_probs, targets, input_lengths,
                                     target_lengths, out, N);
}